// round 2
// baseline (speedup 1.0000x reference)
#include <cuda_runtime.h>

// Shapes (fixed by the problem)
#define BB   64
#define NN   64
#define DD   24
#define HH   256
#define EPN  63      // edges per receiving node
#define ETOT 4032    // N*(N-1)

// Scratch (no allocations allowed -> __device__ globals)
__device__ float g_X  [BB*NN*DD];        // x at t=0
__device__ float g_Hs [2][BB*NN*HH];     // x @ W1[k][0:24]   (send part)
__device__ float g_Hr [2][BB*NN*HH];     // x @ W1[k][24:48] + b1[k]  (recv part, bias folded)
__device__ float g_agg[BB*NN*HH];        // aggregated messages
__device__ float g_Q  [BB*NN];           // per-(b,n) scalar q

// ---------------------------------------------------------------------------
// Kernel A: build x (t=0) and per-node first-layer projections.
// grid = B*N blocks, 256 threads (one per hidden unit)
// ---------------------------------------------------------------------------
__global__ __launch_bounds__(256) void nodeproj_kernel(
    const float* __restrict__ data,   // (B,N,T,16)
    const float* __restrict__ act,    // (B,N,T,8)
    const float* __restrict__ W1,     // (2,48,256)
    const float* __restrict__ b1)     // (2,256)
{
    int bn = blockIdx.x;
    int h  = threadIdx.x;
    __shared__ float xs[DD];
    if (h < 16)       xs[h] = data[bn*32 + h];          // t=0 slice of data
    else if (h < 24)  xs[h] = act [bn*16 + (h-16)];     // t=0 slice of act
    __syncthreads();
    if (h < DD) g_X[bn*DD + h] = xs[h];

    float xr[DD];
#pragma unroll
    for (int d = 0; d < DD; d++) xr[d] = xs[d];

#pragma unroll
    for (int k = 0; k < 2; k++) {
        float hs = 0.f;
        float hr = b1[k*HH + h];
#pragma unroll
        for (int d = 0; d < DD; d++) {
            hs = fmaf(xr[d], W1[(k*48 +      d)*HH + h], hs);
            hr = fmaf(xr[d], W1[(k*48 + 24 + d)*HH + h], hr);
        }
        g_Hs[k][bn*HH + h] = hs;
        g_Hr[k][bn*HH + h] = hr;
    }
}

// ---------------------------------------------------------------------------
// Kernel B (dominant): per (b, n_recv) block.
//   h1[j][:]  = relu(Hs[k][send(j)] + Hr'[k][n])          (63 rows, pad to 64)
//   h2        = relu(h1 @ W2[k] + b2[k])
//   agg[n]   += sum_j relw[j] * h2[j]                     (relw from edges)
// 64x256x256 fp32 GEMM per (b,n,k), 8x8 register tile per thread,
// W2 staged through smem in 32-row tiles.
// ---------------------------------------------------------------------------
#define H1T_STRIDE 68   // 64 + 4 pad: keeps float4 alignment, breaks bank conflicts

extern __shared__ float smemB[];

__global__ __launch_bounds__(256, 2) void edge_kernel(
    const float* __restrict__ edges,  // (B,4032,2)
    const float* __restrict__ W2,     // (2,256,256)
    const float* __restrict__ b2)     // (2,256)
{
    float* h1T   = smemB;                    // [256][68]  h1 transposed: h1T[kk][j]
    float* w2s   = h1T  + 256*H1T_STRIDE;    // [32][256]  W2 k-tile
    float* hrown = w2s  + 32*256;            // [256]
    float* b2s   = hrown + 256;              // [256]
    float* relw  = b2s  + 256;               // [64]
    float* aggsm = relw + 64;                // [256]

    const int bn  = blockIdx.x;
    const int b   = bn >> 6;
    const int n   = bn & 63;
    const int tid = threadIdx.x;
    const int tx  = tid & 31;                // 32 column groups (cols tx + 32*c)
    const int ty  = tid >> 5;                // 8 row groups   (rows ty*8 + r)

    aggsm[tid] = 0.f;

    for (int k = 0; k < 2; k++) {
        __syncthreads();   // protect smem reuse across k iterations
        hrown[tid] = g_Hr[k][bn*HH + tid];
        b2s[tid]   = b2[k*HH + tid];
        if (tid < 64)
            relw[tid] = (tid < EPN) ? edges[(b*ETOT + n*EPN + tid)*2 + k] : 0.f;
        __syncthreads();

        // Build h1T: warp ty handles rows j = ty*8 .. ty*8+7
        for (int i = 0; i < 8; i++) {
            int j = ty*8 + i;
            int s = j + (j >= n); if (s > 63) s = 63;   // row 63 is padding, relw=0 kills it
            const float* row = g_Hs[k] + (b*NN + s)*HH;
#pragma unroll
            for (int u = 0; u < 8; u++) {
                int kk = tx + u*32;
                h1T[kk*H1T_STRIDE + j] = fmaxf(row[kk] + hrown[kk], 0.f);
            }
        }

        float acc[8][8];
#pragma unroll
        for (int r = 0; r < 8; r++)
#pragma unroll
            for (int c = 0; c < 8; c++) acc[r][c] = 0.f;

        for (int kt = 0; kt < 8; kt++) {
            __syncthreads();
            // Stage W2 rows [kt*32, kt*32+32) x 256 cols (contiguous 8192 floats)
            const float4* wg   = (const float4*)(W2 + (k*HH + kt*32)*HH);
            float4*       w2s4 = (float4*)w2s;
#pragma unroll
            for (int i = 0; i < 8; i++) w2s4[tid + i*256] = wg[tid + i*256];
            __syncthreads();

#pragma unroll 4
            for (int kkl = 0; kkl < 32; kkl++) {
                const float* h1row = &h1T[(kt*32 + kkl)*H1T_STRIDE + ty*8];
                float4 a0 = *(const float4*)(h1row);
                float4 a1 = *(const float4*)(h1row + 4);
                float a[8] = {a0.x,a0.y,a0.z,a0.w,a1.x,a1.y,a1.z,a1.w};
                float w[8];
#pragma unroll
                for (int c = 0; c < 8; c++) w[c] = w2s[kkl*256 + tx + 32*c];
#pragma unroll
                for (int r = 0; r < 8; r++)
#pragma unroll
                    for (int c = 0; c < 8; c++)
                        acc[r][c] = fmaf(a[r], w[c], acc[r][c]);
            }
        }

        // Epilogue: bias, relu, edge-weighted row reduction into aggsm
#pragma unroll
        for (int c = 0; c < 8; c++) {
            int col = tx + 32*c;
            float bias = b2s[col];
            float part = 0.f;
#pragma unroll
            for (int r = 0; r < 8; r++) {
                float v = fmaxf(acc[r][c] + bias, 0.f);
                part = fmaf(relw[ty*8 + r], v, part);
            }
            atomicAdd(&aggsm[col], part);
        }
    }
    __syncthreads();
    g_agg[bn*HH + tid] = aggsm[tid];
}

// ---------------------------------------------------------------------------
// Kernel C: out-MLP per (b,n): [x,agg](280) ->256 ->256 ->24, residual, dot W_q2
// ---------------------------------------------------------------------------
__global__ __launch_bounds__(256) void out_kernel(
    const float* __restrict__ Wo1, const float* __restrict__ bo1,
    const float* __restrict__ Wo2, const float* __restrict__ bo2,
    const float* __restrict__ Wo3, const float* __restrict__ bo3,
    const float* __restrict__ Wq2, const float* __restrict__ bq2)
{
    __shared__ float aug[280];
    __shared__ float h1s[256];
    __shared__ float h2s[256];
    __shared__ float pq[24];
    const int bn  = blockIdx.x;
    const int tid = threadIdx.x;

    if (tid < 24) aug[tid] = g_X[bn*DD + tid];
    aug[24 + tid] = g_agg[bn*HH + tid];
    __syncthreads();

    float s = bo1[tid];
    for (int i = 0; i < 280; i++) s = fmaf(aug[i], Wo1[i*256 + tid], s);
    h1s[tid] = fmaxf(s, 0.f);
    __syncthreads();

    s = bo2[tid];
    for (int i = 0; i < 256; i++) s = fmaf(h1s[i], Wo2[i*256 + tid], s);
    h2s[tid] = fmaxf(s, 0.f);
    __syncthreads();

    if (tid < 24) {
        s = bo3[tid];
        for (int i = 0; i < 256; i++) s = fmaf(h2s[i], Wo3[i*24 + tid], s);
        float pred = aug[tid] + s;          // residual x + p
        pq[tid] = pred * Wq2[tid];
    }
    __syncthreads();
    if (tid == 0) {
        float q = bq2[0];
#pragma unroll
        for (int d = 0; d < 24; d++) q += pq[d];
        g_Q[bn] = q;
    }
}

// ---------------------------------------------------------------------------
// Kernel D: out[b] = sum_n Q[b][n]*Wq3[n] + bq3
// ---------------------------------------------------------------------------
__global__ void q_kernel(const float* __restrict__ Wq3,
                         const float* __restrict__ bq3,
                         float* __restrict__ out)
{
    const int b = blockIdx.x;
    const int n = threadIdx.x;  // 64
    __shared__ float red[64];
    red[n] = g_Q[b*NN + n] * Wq3[n];
    __syncthreads();
    for (int off = 32; off > 0; off >>= 1) {
        if (n < off) red[n] += red[n + off];
        __syncthreads();
    }
    if (n == 0) out[b] = red[0] + bq3[0];
}

// ---------------------------------------------------------------------------
extern "C" void kernel_launch(void* const* d_in, const int* in_sizes, int n_in,
                              void* d_out, int out_size)
{
    const float* data  = (const float*)d_in[0];
    const float* act   = (const float*)d_in[1];
    const float* edges = (const float*)d_in[2];
    // d_in[3] rel_rec, d_in[4] rel_send: structure known analytically
    // d_in[5] prediction_steps == 1 (fixed)
    const float* W1  = (const float*)d_in[6];
    const float* b1  = (const float*)d_in[7];
    const float* W2  = (const float*)d_in[8];
    const float* b2  = (const float*)d_in[9];
    const float* Wo1 = (const float*)d_in[10];
    const float* bo1 = (const float*)d_in[11];
    const float* Wo2 = (const float*)d_in[12];
    const float* bo2 = (const float*)d_in[13];
    const float* Wo3 = (const float*)d_in[14];
    const float* bo3 = (const float*)d_in[15];
    const float* Wq2 = (const float*)d_in[16];
    const float* bq2 = (const float*)d_in[17];
    const float* Wq3 = (const float*)d_in[18];
    const float* bq3 = (const float*)d_in[19];
    float* out = (float*)d_out;

    nodeproj_kernel<<<BB*NN, 256>>>(data, act, W1, b1);

    size_t smem_bytes = (256*H1T_STRIDE + 32*256 + 256 + 256 + 64 + 256) * sizeof(float);
    cudaFuncSetAttribute(edge_kernel, cudaFuncAttributeMaxDynamicSharedMemorySize,
                         (int)smem_bytes);
    edge_kernel<<<BB*NN, 256, smem_bytes>>>(edges, W2, b2);

    out_kernel<<<BB*NN, 256>>>(Wo1, bo1, Wo2, bo2, Wo3, bo3, Wq2, bq2);
    q_kernel<<<BB, 64>>>(Wq3, bq3, out);
}

// round 4
// speedup vs baseline: 1.7441x; 1.7441x over previous
#include <cuda_runtime.h>
#include <cuda_bf16.h>
#include <cstdint>

// ---------------------------------------------------------------- shapes
#define BB   64
#define NN   64
#define DD   24
#define HH   256
#define EPN  63
#define ETOT 4032

// ---------------------------------------------------------------- scratch
__device__ float g_X  [BB*NN*DD];
__device__ float g_Hs [2][BB*NN*HH];
__device__ float g_Hr [2][BB*NN*HH];
__device__ float g_agg[BB*NN*HH];
__device__ float g_Q  [BB*NN];
__device__ __nv_bfloat16 g_w2t_hi[2][HH*HH];   // W2^T: [k][n][kk]  (n-major)
__device__ __nv_bfloat16 g_w2t_lo[2][HH*HH];

// ---------------------------------------------------------------- mma helper
__device__ __forceinline__ void mma16816(float* c, const uint32_t* a, const uint32_t* b) {
    asm volatile(
        "mma.sync.aligned.m16n8k16.row.col.f32.bf16.bf16.f32 "
        "{%0,%1,%2,%3}, {%4,%5,%6,%7}, {%8,%9}, {%0,%1,%2,%3};\n"
        : "+f"(c[0]), "+f"(c[1]), "+f"(c[2]), "+f"(c[3])
        : "r"(a[0]), "r"(a[1]), "r"(a[2]), "r"(a[3]), "r"(b[0]), "r"(b[1]));
}

__device__ __forceinline__ uint32_t pack_bf16(float x, float y) {
    __nv_bfloat16 hx = __float2bfloat16_rn(x);
    __nv_bfloat16 hy = __float2bfloat16_rn(y);
    return ((uint32_t)__bfloat16_as_ushort(hy) << 16) | __bfloat16_as_ushort(hx);
}

// ---------------------------------------------------------------- W prep: split W2^T to bf16 hi/lo
__global__ __launch_bounds__(256) void wprep_kernel(const float* __restrict__ W2) {
    int k  = blockIdx.x >> 8;
    int c  = blockIdx.x & 255;      // output col (n)
    int kk = threadIdx.x;           // input row (k)
    float x = W2[(k*HH + kk)*HH + c];
    __nv_bfloat16 hi = __float2bfloat16_rn(x);
    __nv_bfloat16 lo = __float2bfloat16_rn(x - __bfloat162float(hi));
    g_w2t_hi[k][c*HH + kk] = hi;
    g_w2t_lo[k][c*HH + kk] = lo;
}

// ---------------------------------------------------------------- node projections
__global__ __launch_bounds__(256) void nodeproj_kernel(
    const float* __restrict__ data, const float* __restrict__ act,
    const float* __restrict__ W1, const float* __restrict__ b1)
{
    int bn = blockIdx.x;
    int h  = threadIdx.x;
    __shared__ float xs[DD];
    if (h < 16)      xs[h] = data[bn*32 + h];
    else if (h < 24) xs[h] = act [bn*16 + (h-16)];
    __syncthreads();
    if (h < DD) g_X[bn*DD + h] = xs[h];

    float xr[DD];
#pragma unroll
    for (int d = 0; d < DD; d++) xr[d] = xs[d];
#pragma unroll
    for (int k = 0; k < 2; k++) {
        float hs = 0.f, hr = b1[k*HH + h];
#pragma unroll
        for (int d = 0; d < DD; d++) {
            hs = fmaf(xr[d], W1[(k*48 +      d)*HH + h], hs);
            hr = fmaf(xr[d], W1[(k*48 + 24 + d)*HH + h], hr);
        }
        g_Hs[k][bn*HH + h] = hs;
        g_Hr[k][bn*HH + h] = hr;
    }
}

// ---------------------------------------------------------------- edge GEMM (mma.sync bf16 3-pass)
// SMEM byte offsets
#define AST 264                        // A k-stride (bf16 elems): 256 + 8 pad
#define BST 72                         // B k-stride: 64 + 8 pad
#define A_HI   0
#define A_LO   (A_HI + 128*AST*2)      // 67584
#define B_HI   (A_LO + 128*AST*2)      // 135168
#define B_LO   (B_HI + 128*BST*2)      // 153600
#define HROW_O (B_LO + 128*BST*2)      // 172032 : float[512]
#define B2S_O  (HROW_O + 512*4)        // float[256]
#define RELW_O (B2S_O  + 256*4)        // float[128]
#define AGG_O  (RELW_O + 128*4)        // float[512]
#define EDGE_SMEM (AGG_O + 512*4)      // 177664 bytes

extern __shared__ __align__(16) char smem[];

__global__ __launch_bounds__(256, 1) void edge_kernel(
    const float* __restrict__ edges, const float* __restrict__ b2)
{
    __nv_bfloat16* Ahi = (__nv_bfloat16*)(smem + A_HI);
    __nv_bfloat16* Alo = (__nv_bfloat16*)(smem + A_LO);
    __nv_bfloat16* Bhi = (__nv_bfloat16*)(smem + B_HI);
    __nv_bfloat16* Blo = (__nv_bfloat16*)(smem + B_LO);
    float* hrow  = (float*)(smem + HROW_O);
    float* b2s   = (float*)(smem + B2S_O);
    float* relw  = (float*)(smem + RELW_O);
    float* aggsm = (float*)(smem + AGG_O);

    const int tid = threadIdx.x;
    const int wid = tid >> 5, lid = tid & 31;
    const int wm  = wid & 3;             // m-group: rows wm*32..+32
    const int wn  = wid >> 2;            // n-group within half: cols wn*64..+64
    const int qr  = lid >> 2;            // fragment row/col offset within tile
    const int qc  = (lid & 3) * 2;
    const int b   = blockIdx.x >> 5;
    const int g   = blockIdx.x & 31;
    const int n0  = 2*g, n1 = 2*g + 1;
    const int recvsel = wm >> 1;         // 0 -> n0 rows, 1 -> n1 rows

    aggsm[tid] = 0.f;
    aggsm[tid + 256] = 0.f;

    for (int k = 0; k < 2; k++) {
        __syncthreads();  // prior-iteration readers done before restaging
        hrow[tid]       = g_Hr[k][((b<<6) + n0)*HH + tid];
        hrow[256 + tid] = g_Hr[k][((b<<6) + n1)*HH + tid];
        b2s[tid]        = b2[k*HH + tid];
        if (tid < 128) {
            int recv = (tid < 64) ? n0 : n1, jl = tid & 63;
            relw[tid] = (jl < EPN) ? edges[((b*ETOT) + recv*EPN + jl)*2 + k] : 0.f;
        }
        __syncthreads();

        // ---- build A = relu(Hs[send]+Hr[recv]) -> bf16 hi/lo, rows 0..127, k 0..255
        {
            int j = tid >> 1, half = tid & 1;
            int recv = (j < 64) ? n0 : n1;
            int jl = j & 63;
            int s = jl + (jl >= recv); if (s > 63) s = 63;   // pad row killed by relw=0
            const float* hs = &g_Hs[k][((b<<6) + s)*HH];
            const float* hr = &hrow[(j >= 64) ? 256 : 0];
            __nv_bfloat16* ah = Ahi + j*AST;
            __nv_bfloat16* al = Alo + j*AST;
#pragma unroll 8
            for (int kk = half*128; kk < half*128 + 128; kk += 4) {
                float4 v = *(const float4*)(hs + kk);
                float r0 = fmaxf(v.x + hr[kk  ], 0.f);
                float r1 = fmaxf(v.y + hr[kk+1], 0.f);
                float r2 = fmaxf(v.z + hr[kk+2], 0.f);
                float r3 = fmaxf(v.w + hr[kk+3], 0.f);
                uint32_t h0 = pack_bf16(r0, r1), h1 = pack_bf16(r2, r3);
                float q0 = r0 - __bfloat162float(__ushort_as_bfloat16((uint16_t)h0));
                float q1 = r1 - __bfloat162float(__ushort_as_bfloat16((uint16_t)(h0>>16)));
                float q2 = r2 - __bfloat162float(__ushort_as_bfloat16((uint16_t)h1));
                float q3 = r3 - __bfloat162float(__ushort_as_bfloat16((uint16_t)(h1>>16)));
                *(uint32_t*)(ah + kk)     = h0;
                *(uint32_t*)(ah + kk + 2) = h1;
                *(uint32_t*)(al + kk)     = pack_bf16(q0, q1);
                *(uint32_t*)(al + kk + 2) = pack_bf16(q2, q3);
            }
        }
        // (A visible to all after the sync inside the first chunk below)

        for (int nh = 0; nh < 2; nh++) {
            float acc[2][8][4];
#pragma unroll
            for (int mt = 0; mt < 2; mt++)
#pragma unroll
                for (int nt = 0; nt < 8; nt++)
#pragma unroll
                    for (int r = 0; r < 4; r++) acc[mt][nt][r] = 0.f;

            for (int c = 0; c < 4; c++) {
                __syncthreads();   // previous chunk readers done (also fences A build)
                // stage B chunk: n = nh*128 .. +128, kk = c*64 .. +64
                {
                    const __nv_bfloat16* wh = g_w2t_hi[k] + (nh*128)*HH + c*64;
                    const __nv_bfloat16* wl = g_w2t_lo[k] + (nh*128)*HH + c*64;
#pragma unroll
                    for (int it = 0; it < 16; it++) {
                        int p = tid + it*256;          // 4096 pairs
                        int nl = p >> 5, kkl = (p & 31)*2;
                        *(uint32_t*)(Bhi + nl*BST + kkl) = *(const uint32_t*)(wh + nl*HH + kkl);
                        *(uint32_t*)(Blo + nl*BST + kkl) = *(const uint32_t*)(wl + nl*HH + kkl);
                    }
                }
                __syncthreads();

#pragma unroll
                for (int kt = 0; kt < 4; kt++) {
                    const int kk0 = c*64 + kt*16 + qc;
                    uint32_t aH[2][4], aL[2][4];
#pragma unroll
                    for (int mt = 0; mt < 2; mt++) {
                        int base = (wm*32 + mt*16 + qr)*AST + kk0;
                        aH[mt][0] = *(const uint32_t*)(Ahi + base);
                        aH[mt][1] = *(const uint32_t*)(Ahi + base + 8*AST);
                        aH[mt][2] = *(const uint32_t*)(Ahi + base + 8);
                        aH[mt][3] = *(const uint32_t*)(Ahi + base + 8*AST + 8);
                        aL[mt][0] = *(const uint32_t*)(Alo + base);
                        aL[mt][1] = *(const uint32_t*)(Alo + base + 8*AST);
                        aL[mt][2] = *(const uint32_t*)(Alo + base + 8);
                        aL[mt][3] = *(const uint32_t*)(Alo + base + 8*AST + 8);
                    }
                    uint32_t bH[8][2], bL[8][2];
                    const int kb = kt*16 + qc;
#pragma unroll
                    for (int nt = 0; nt < 8; nt++) {
                        int nb = (wn*64 + nt*8 + qr)*BST + kb;
                        bH[nt][0] = *(const uint32_t*)(Bhi + nb);
                        bH[nt][1] = *(const uint32_t*)(Bhi + nb + 8);
                        bL[nt][0] = *(const uint32_t*)(Blo + nb);
                        bL[nt][1] = *(const uint32_t*)(Blo + nb + 8);
                    }
#pragma unroll
                    for (int mt = 0; mt < 2; mt++)
#pragma unroll
                        for (int nt = 0; nt < 8; nt++) {
                            mma16816(acc[mt][nt], aH[mt], bH[nt]);
                            mma16816(acc[mt][nt], aH[mt], bL[nt]);
                            mma16816(acc[mt][nt], aL[mt], bH[nt]);
                        }
                }
            }

            // ---- epilogue: v = relu(D+b2)*relw, reduce rows, accumulate into aggsm
#pragma unroll
            for (int nt = 0; nt < 8; nt++) {
                int col0 = nh*128 + wn*64 + nt*8 + qc;
                float bb0 = b2s[col0], bb1 = b2s[col0 + 1];
                float v0 = 0.f, v1 = 0.f;
#pragma unroll
                for (int mt = 0; mt < 2; mt++) {
                    int r0 = wm*32 + mt*16 + qr;
                    float w0 = relw[r0], w1 = relw[r0 + 8];
                    v0 += w0*fmaxf(acc[mt][nt][0] + bb0, 0.f)
                        + w1*fmaxf(acc[mt][nt][2] + bb0, 0.f);
                    v1 += w0*fmaxf(acc[mt][nt][1] + bb1, 0.f)
                        + w1*fmaxf(acc[mt][nt][3] + bb1, 0.f);
                }
                v0 += __shfl_xor_sync(0xffffffffu, v0, 4);
                v0 += __shfl_xor_sync(0xffffffffu, v0, 8);
                v0 += __shfl_xor_sync(0xffffffffu, v0, 16);
                v1 += __shfl_xor_sync(0xffffffffu, v1, 4);
                v1 += __shfl_xor_sync(0xffffffffu, v1, 8);
                v1 += __shfl_xor_sync(0xffffffffu, v1, 16);
                if (lid < 4) {
                    atomicAdd(&aggsm[recvsel*256 + col0    ], v0);
                    atomicAdd(&aggsm[recvsel*256 + col0 + 1], v1);
                }
            }
        }
    }
    __syncthreads();
    g_agg[((b<<6) + n0)*HH + tid] = aggsm[tid];
    g_agg[((b<<6) + n1)*HH + tid] = aggsm[256 + tid];
}

// ---------------------------------------------------------------- out-MLP
__global__ __launch_bounds__(256) void out_kernel(
    const float* __restrict__ Wo1, const float* __restrict__ bo1,
    const float* __restrict__ Wo2, const float* __restrict__ bo2,
    const float* __restrict__ Wo3, const float* __restrict__ bo3,
    const float* __restrict__ Wq2, const float* __restrict__ bq2)
{
    __shared__ float aug[280];
    __shared__ float h1s[256];
    __shared__ float h2s[256];
    __shared__ float pq[24];
    const int bn = blockIdx.x;
    const int tid = threadIdx.x;

    if (tid < 24) aug[tid] = g_X[bn*DD + tid];
    aug[24 + tid] = g_agg[bn*HH + tid];
    __syncthreads();

    float s = bo1[tid];
    for (int i = 0; i < 280; i++) s = fmaf(aug[i], Wo1[i*256 + tid], s);
    h1s[tid] = fmaxf(s, 0.f);
    __syncthreads();

    s = bo2[tid];
    for (int i = 0; i < 256; i++) s = fmaf(h1s[i], Wo2[i*256 + tid], s);
    h2s[tid] = fmaxf(s, 0.f);
    __syncthreads();

    if (tid < 24) {
        s = bo3[tid];
        for (int i = 0; i < 256; i++) s = fmaf(h2s[i], Wo3[i*24 + tid], s);
        pq[tid] = (aug[tid] + s) * Wq2[tid];
    }
    __syncthreads();
    if (tid == 0) {
        float q = bq2[0];
#pragma unroll
        for (int d = 0; d < 24; d++) q += pq[d];
        g_Q[bn] = q;
    }
}

// ---------------------------------------------------------------- final dot
__global__ void q_kernel(const float* __restrict__ Wq3,
                         const float* __restrict__ bq3,
                         float* __restrict__ out)
{
    const int b = blockIdx.x;
    const int n = threadIdx.x;
    __shared__ float red[64];
    red[n] = g_Q[b*NN + n] * Wq3[n];
    __syncthreads();
    for (int off = 32; off > 0; off >>= 1) {
        if (n < off) red[n] += red[n + off];
        __syncthreads();
    }
    if (n == 0) out[b] = red[0] + bq3[0];
}

// ----------------------------------------------------------------
extern "C" void kernel_launch(void* const* d_in, const int* in_sizes, int n_in,
                              void* d_out, int out_size)
{
    const float* data  = (const float*)d_in[0];
    const float* act   = (const float*)d_in[1];
    const float* edges = (const float*)d_in[2];
    const float* W1  = (const float*)d_in[6];
    const float* b1  = (const float*)d_in[7];
    const float* W2  = (const float*)d_in[8];
    const float* b2  = (const float*)d_in[9];
    const float* Wo1 = (const float*)d_in[10];
    const float* bo1 = (const float*)d_in[11];
    const float* Wo2 = (const float*)d_in[12];
    const float* bo2 = (const float*)d_in[13];
    const float* Wo3 = (const float*)d_in[14];
    const float* bo3 = (const float*)d_in[15];
    const float* Wq2 = (const float*)d_in[16];
    const float* bq2 = (const float*)d_in[17];
    const float* Wq3 = (const float*)d_in[18];
    const float* bq3 = (const float*)d_in[19];
    float* out = (float*)d_out;

    wprep_kernel<<<512, 256>>>(W2);
    nodeproj_kernel<<<BB*NN, 256>>>(data, act, W1, b1);

    cudaFuncSetAttribute(edge_kernel, cudaFuncAttributeMaxDynamicSharedMemorySize,
                         EDGE_SMEM);
    edge_kernel<<<BB*NN/2, 256, EDGE_SMEM>>>(edges, b2);

    out_kernel<<<BB*NN, 256>>>(Wo1, bo1, Wo2, bo2, Wo3, bo3, Wq2, bq2);
    q_kernel<<<BB, 64>>>(Wq3, bq3, out);
}

// round 5
// speedup vs baseline: 1.9471x; 1.1164x over previous
#include <cuda_runtime.h>
#include <cuda_bf16.h>
#include <cstdint>

// ---------------------------------------------------------------- shapes
#define BB   64
#define NN   64
#define DD   24
#define HH   256
#define EPN  63
#define ETOT 4032

// ---------------------------------------------------------------- scratch
__device__ float g_X  [BB*NN*DD];
__device__ float g_Hs [2][BB*NN*HH];
__device__ float g_Hr [2][BB*NN*HH];
__device__ float g_agg[BB*NN*HH];
__device__ float g_Q  [BB*NN];
__device__ __align__(16) __nv_bfloat16 g_w2t_hi[2][HH*HH];   // W2^T: [k][n][kk]
__device__ __align__(16) __nv_bfloat16 g_w2t_lo[2][HH*HH];

// ---------------------------------------------------------------- helpers
__device__ __forceinline__ void mma16816(float* c, const uint32_t* a, const uint32_t* b) {
    asm volatile(
        "mma.sync.aligned.m16n8k16.row.col.f32.bf16.bf16.f32 "
        "{%0,%1,%2,%3}, {%4,%5,%6,%7}, {%8,%9}, {%0,%1,%2,%3};\n"
        : "+f"(c[0]), "+f"(c[1]), "+f"(c[2]), "+f"(c[3])
        : "r"(a[0]), "r"(a[1]), "r"(a[2]), "r"(a[3]), "r"(b[0]), "r"(b[1]));
}
#define LDM_X4(r, addr) \
    asm volatile("ldmatrix.sync.aligned.m8n8.x4.shared.b16 {%0,%1,%2,%3}, [%4];" \
        : "=r"((r)[0]), "=r"((r)[1]), "=r"((r)[2]), "=r"((r)[3]) : "r"(addr))

__device__ __forceinline__ void cp16(uint32_t dst, const void* src) {
    asm volatile("cp.async.cg.shared.global [%0], [%1], 16;\n" :: "r"(dst), "l"(src) : "memory");
}
#define CP_COMMIT() asm volatile("cp.async.commit_group;\n" ::: "memory")

__device__ __forceinline__ uint32_t smem_u32(const void* p) {
    uint32_t a;
    asm("{ .reg .u64 t; cvta.to.shared.u64 t, %1; cvt.u32.u64 %0, t; }" : "=r"(a) : "l"(p));
    return a;
}
__device__ __forceinline__ uint32_t pack_bf16(float x, float y) {
    __nv_bfloat16 hx = __float2bfloat16_rn(x);
    __nv_bfloat16 hy = __float2bfloat16_rn(y);
    return ((uint32_t)__bfloat16_as_ushort(hy) << 16) | __bfloat16_as_ushort(hx);
}

// ---------------------------------------------------------------- W prep
__global__ __launch_bounds__(256) void wprep_kernel(const float* __restrict__ W2) {
    int k  = blockIdx.x >> 8;
    int c  = blockIdx.x & 255;
    int kk = threadIdx.x;
    float x = W2[(k*HH + kk)*HH + c];
    __nv_bfloat16 hi = __float2bfloat16_rn(x);
    __nv_bfloat16 lo = __float2bfloat16_rn(x - __bfloat162float(hi));
    g_w2t_hi[k][c*HH + kk] = hi;
    g_w2t_lo[k][c*HH + kk] = lo;
}

// ---------------------------------------------------------------- node projections
__global__ __launch_bounds__(256) void nodeproj_kernel(
    const float* __restrict__ data, const float* __restrict__ act,
    const float* __restrict__ W1, const float* __restrict__ b1)
{
    int bn = blockIdx.x;
    int h  = threadIdx.x;
    __shared__ float xs[DD];
    if (h < 16)      xs[h] = data[bn*32 + h];
    else if (h < 24) xs[h] = act [bn*16 + (h-16)];
    __syncthreads();
    if (h < DD) g_X[bn*DD + h] = xs[h];

    float xr[DD];
#pragma unroll
    for (int d = 0; d < DD; d++) xr[d] = xs[d];
#pragma unroll
    for (int k = 0; k < 2; k++) {
        float hs = 0.f, hr = b1[k*HH + h];
#pragma unroll
        for (int d = 0; d < DD; d++) {
            hs = fmaf(xr[d], W1[(k*48 +      d)*HH + h], hs);
            hr = fmaf(xr[d], W1[(k*48 + 24 + d)*HH + h], hr);
        }
        g_Hs[k][bn*HH + h] = hs;
        g_Hr[k][bn*HH + h] = hr;
    }
}

// ---------------------------------------------------------------- edge GEMM
// SMEM layout (bytes)
#define AST 264                       // A k-stride (elems): 256 + 8
#define BST 72                        // B k-stride (elems): 64 + 8
#define A_HI   0
#define A_LO   67584                  // 128*264*2
#define B_OFF  135168
#define BSPLIT 18432                  // 128*72*2
#define BUFSZ  36864                  // hi+lo per buffer
#define MISC   208896                 // B_OFF + 2*BUFSZ
// misc floats: hrow[512], b2s[256], relw[128], aggsm[512]
#define EDGE_SMEM (MISC + 1408*4)     // 214528

extern __shared__ __align__(16) char smem[];

__device__ __forceinline__ void stageB(int k, int nh, int c, int buf,
                                       int tid, uint32_t sb) {
    const __nv_bfloat16* wh = g_w2t_hi[k] + (nh*128)*HH + c*64;
    const __nv_bfloat16* wl = g_w2t_lo[k] + (nh*128)*HH + c*64;
    uint32_t bh = sb + B_OFF + buf*BUFSZ;
    uint32_t bl = bh + BSPLIT;
#pragma unroll
    for (int o = 0; o < 4; o++) {
        int opid = tid + o*256;          // 0..1023
        int n = opid >> 3, part = opid & 7;
        uint32_t doff = (uint32_t)(n*BST + part*8)*2;
        cp16(bh + doff, wh + n*HH + part*8);
        cp16(bl + doff, wl + n*HH + part*8);
    }
}

__global__ __launch_bounds__(256, 1) void edge_kernel(
    const float* __restrict__ edges, const float* __restrict__ b2)
{
    const uint32_t sb = smem_u32(smem);
    float* hrow  = (float*)(smem + MISC);
    float* b2s   = (float*)(smem + MISC + 512*4);
    float* relw  = (float*)(smem + MISC + 768*4);
    float* aggsm = (float*)(smem + MISC + 896*4);

    const int tid = threadIdx.x;
    const int wid = tid >> 5, lid = tid & 31;
    const int wm  = wid & 3;             // row group
    const int wn  = wid >> 2;            // col group within nh-half
    const int qr  = lid >> 2;
    const int qc  = (lid & 3) * 2;
    const int b   = blockIdx.x >> 5;
    const int g   = blockIdx.x & 31;
    const int n0  = 2*g, n1 = 2*g + 1;
    const int recvsel = wm >> 1;

    // lane-invariant ldmatrix address pieces
    const int arow    = wm*32 + (lid & 15);
    const int acolsel = (lid & 16) ? 8 : 0;
    const int brow    = wn*64 + ((lid & 16) ? 8 : 0) + (lid & 7);
    const int bksel   = (lid & 8) ? 8 : 0;

    aggsm[tid] = 0.f;
    aggsm[tid + 256] = 0.f;

    for (int k = 0; k < 2; k++) {
        __syncthreads();
        hrow[tid]       = g_Hr[k][((b<<6) + n0)*HH + tid];
        hrow[256 + tid] = g_Hr[k][((b<<6) + n1)*HH + tid];
        b2s[tid]        = b2[k*HH + tid];
        if (tid < 128) {
            int recv = (tid < 64) ? n0 : n1, jl = tid & 63;
            relw[tid] = (jl < EPN) ? edges[((b*ETOT) + recv*EPN + jl)*2 + k] : 0.f;
        }
        __syncthreads();

        // prefetch first B chunk, then build A (overlaps with cp.async)
        stageB(k, 0, 0, 0, tid, sb);
        CP_COMMIT();

        {   // ---- build A = relu(Hs[send]+Hr[recv]) -> bf16 hi/lo
            int j = tid >> 1, half = tid & 1;
            int recv = (j < 64) ? n0 : n1;
            int jl = j & 63;
            int s = jl + (jl >= recv); if (s > 63) s = 63;  // pad row, relw=0
            const float* hs = &g_Hs[k][((b<<6) + s)*HH];
            const float* hr = &hrow[(j >= 64) ? 256 : 0];
            __nv_bfloat16* ah = (__nv_bfloat16*)(smem + A_HI) + j*AST;
            __nv_bfloat16* al = (__nv_bfloat16*)(smem + A_LO) + j*AST;
#pragma unroll 8
            for (int kk = half*128; kk < half*128 + 128; kk += 4) {
                float4 v = *(const float4*)(hs + kk);
                float r0 = fmaxf(v.x + hr[kk  ], 0.f);
                float r1 = fmaxf(v.y + hr[kk+1], 0.f);
                float r2 = fmaxf(v.z + hr[kk+2], 0.f);
                float r3 = fmaxf(v.w + hr[kk+3], 0.f);
                uint32_t h0 = pack_bf16(r0, r1), h1 = pack_bf16(r2, r3);
                float q0 = r0 - __bfloat162float(__ushort_as_bfloat16((uint16_t)h0));
                float q1 = r1 - __bfloat162float(__ushort_as_bfloat16((uint16_t)(h0>>16)));
                float q2 = r2 - __bfloat162float(__ushort_as_bfloat16((uint16_t)h1));
                float q3 = r3 - __bfloat162float(__ushort_as_bfloat16((uint16_t)(h1>>16)));
                *(uint32_t*)(ah + kk)     = h0;
                *(uint32_t*)(ah + kk + 2) = h1;
                *(uint32_t*)(al + kk)     = pack_bf16(q0, q1);
                *(uint32_t*)(al + kk + 2) = pack_bf16(q2, q3);
            }
        }

        for (int nh = 0; nh < 2; nh++) {
            float acc[2][8][4];
#pragma unroll
            for (int mt = 0; mt < 2; mt++)
#pragma unroll
                for (int nt = 0; nt < 8; nt++)
#pragma unroll
                    for (int r = 0; r < 4; r++) acc[mt][nt][r] = 0.f;

            for (int c = 0; c < 4; c++) {
                const int cc = nh*4 + c;
                const bool has_next = (cc < 7);
                if (has_next) {
                    stageB(k, (cc+1) >> 2, (cc+1) & 3, (cc+1) & 1, tid, sb);
                    CP_COMMIT();
                    asm volatile("cp.async.wait_group 1;\n" ::: "memory");
                } else {
                    asm volatile("cp.async.wait_group 0;\n" ::: "memory");
                }
                __syncthreads();   // B chunk cc ready; also fences A build (c==0)

                const uint32_t Bh = sb + B_OFF + (cc & 1)*BUFSZ;
                const uint32_t Bl = Bh + BSPLIT;
#pragma unroll
                for (int kt = 0; kt < 4; kt++) {
                    const int kkb = c*64 + kt*16;
                    uint32_t aH[2][4], aL[2][4];
#pragma unroll
                    for (int mt = 0; mt < 2; mt++) {
                        uint32_t ao = (uint32_t)((arow + mt*16)*AST + kkb + acolsel)*2;
                        LDM_X4(aH[mt], sb + A_HI + ao);
                        LDM_X4(aL[mt], sb + A_LO + ao);
                    }
                    uint32_t bH[8][2], bL[8][2];
#pragma unroll
                    for (int p = 0; p < 4; p++) {
                        uint32_t bo = (uint32_t)((brow + p*16)*BST + kt*16 + bksel)*2;
                        uint32_t t[4];
                        LDM_X4(t, Bh + bo);
                        bH[2*p][0] = t[0]; bH[2*p][1] = t[1];
                        bH[2*p+1][0] = t[2]; bH[2*p+1][1] = t[3];
                        LDM_X4(t, Bl + bo);
                        bL[2*p][0] = t[0]; bL[2*p][1] = t[1];
                        bL[2*p+1][0] = t[2]; bL[2*p+1][1] = t[3];
                    }
#pragma unroll
                    for (int mt = 0; mt < 2; mt++)
#pragma unroll
                        for (int nt = 0; nt < 8; nt++) {
                            mma16816(acc[mt][nt], aH[mt], bH[nt]);
                            mma16816(acc[mt][nt], aH[mt], bL[nt]);
                            mma16816(acc[mt][nt], aL[mt], bH[nt]);
                        }
                }
                __syncthreads();   // all reads of buf (cc&1) done before restage at cc+2
            }

            // ---- epilogue: v = relu(D+b2)*relw, reduce rows, accumulate aggsm
#pragma unroll
            for (int nt = 0; nt < 8; nt++) {
                int col0 = nh*128 + wn*64 + nt*8 + qc;
                float bb0 = b2s[col0], bb1 = b2s[col0 + 1];
                float v0 = 0.f, v1 = 0.f;
#pragma unroll
                for (int mt = 0; mt < 2; mt++) {
                    int r0 = wm*32 + mt*16 + qr;
                    float w0 = relw[r0], w1 = relw[r0 + 8];
                    v0 += w0*fmaxf(acc[mt][nt][0] + bb0, 0.f)
                        + w1*fmaxf(acc[mt][nt][2] + bb0, 0.f);
                    v1 += w0*fmaxf(acc[mt][nt][1] + bb1, 0.f)
                        + w1*fmaxf(acc[mt][nt][3] + bb1, 0.f);
                }
                v0 += __shfl_xor_sync(0xffffffffu, v0, 4);
                v0 += __shfl_xor_sync(0xffffffffu, v0, 8);
                v0 += __shfl_xor_sync(0xffffffffu, v0, 16);
                v1 += __shfl_xor_sync(0xffffffffu, v1, 4);
                v1 += __shfl_xor_sync(0xffffffffu, v1, 8);
                v1 += __shfl_xor_sync(0xffffffffu, v1, 16);
                if (lid < 4) {
                    atomicAdd(&aggsm[recvsel*256 + col0    ], v0);
                    atomicAdd(&aggsm[recvsel*256 + col0 + 1], v1);
                }
            }
        }
    }
    __syncthreads();
    g_agg[((b<<6) + n0)*HH + tid] = aggsm[tid];
    g_agg[((b<<6) + n1)*HH + tid] = aggsm[256 + tid];
}

// ---------------------------------------------------------------- out-MLP: 16 rows/CTA
#define OR 16
__global__ __launch_bounds__(256) void out_kernel(
    const float* __restrict__ Wo1, const float* __restrict__ bo1,
    const float* __restrict__ Wo2, const float* __restrict__ bo2,
    const float* __restrict__ Wo3, const float* __restrict__ bo3,
    const float* __restrict__ Wq2, const float* __restrict__ bq2)
{
    __shared__ __align__(16) float aug[OR][288];
    __shared__ __align__(16) float h1 [OR][264];
    __shared__ __align__(16) float h2 [OR][264];
    __shared__ float pq[OR][24];
    const int bn0 = blockIdx.x * OR;
    const int tid = threadIdx.x;

    {
        int r = tid >> 4, i0 = tid & 15;
        for (int i = i0; i < 280; i += 16)
            aug[r][i] = (i < 24) ? g_X[(bn0+r)*DD + i] : g_agg[(bn0+r)*HH + (i-24)];
    }
    __syncthreads();

    const int col = tid;
    float acc[OR];
#pragma unroll
    for (int r = 0; r < OR; r++) acc[r] = bo1[col];
    for (int i = 0; i < 280; i += 4) {
        float w0 = Wo1[(i  )*HH + col], w1 = Wo1[(i+1)*HH + col];
        float w2 = Wo1[(i+2)*HH + col], w3 = Wo1[(i+3)*HH + col];
#pragma unroll
        for (int r = 0; r < OR; r++) {
            float4 a = *(const float4*)&aug[r][i];
            acc[r] = fmaf(a.x, w0, fmaf(a.y, w1, fmaf(a.z, w2, fmaf(a.w, w3, acc[r]))));
        }
    }
#pragma unroll
    for (int r = 0; r < OR; r++) h1[r][col] = fmaxf(acc[r], 0.f);
    __syncthreads();

#pragma unroll
    for (int r = 0; r < OR; r++) acc[r] = bo2[col];
    for (int i = 0; i < 256; i += 4) {
        float w0 = Wo2[(i  )*HH + col], w1 = Wo2[(i+1)*HH + col];
        float w2 = Wo2[(i+2)*HH + col], w3 = Wo2[(i+3)*HH + col];
#pragma unroll
        for (int r = 0; r < OR; r++) {
            float4 a = *(const float4*)&h1[r][i];
            acc[r] = fmaf(a.x, w0, fmaf(a.y, w1, fmaf(a.z, w2, fmaf(a.w, w3, acc[r]))));
        }
    }
#pragma unroll
    for (int r = 0; r < OR; r++) h2[r][col] = fmaxf(acc[r], 0.f);
    __syncthreads();

    {
        int rr = tid & 15;
        for (int c2 = tid >> 4; c2 < DD; c2 += 16) {
            float s = bo3[c2];
            for (int i = 0; i < 256; i++) s = fmaf(h2[rr][i], Wo3[i*DD + c2], s);
            pq[rr][c2] = (aug[rr][c2] + s) * Wq2[c2];
        }
    }
    __syncthreads();
    if (tid < OR) {
        float q = bq2[0];
#pragma unroll
        for (int d = 0; d < DD; d++) q += pq[tid][d];
        g_Q[bn0 + tid] = q;
    }
}

// ---------------------------------------------------------------- final dot
__global__ void q_kernel(const float* __restrict__ Wq3,
                         const float* __restrict__ bq3,
                         float* __restrict__ out)
{
    const int b = blockIdx.x;
    const int n = threadIdx.x;
    __shared__ float red[64];
    red[n] = g_Q[b*NN + n] * Wq3[n];
    __syncthreads();
    for (int off = 32; off > 0; off >>= 1) {
        if (n < off) red[n] += red[n + off];
        __syncthreads();
    }
    if (n == 0) out[b] = red[0] + bq3[0];
}

// ----------------------------------------------------------------
extern "C" void kernel_launch(void* const* d_in, const int* in_sizes, int n_in,
                              void* d_out, int out_size)
{
    const float* data  = (const float*)d_in[0];
    const float* act   = (const float*)d_in[1];
    const float* edges = (const float*)d_in[2];
    const float* W1  = (const float*)d_in[6];
    const float* b1  = (const float*)d_in[7];
    const float* W2  = (const float*)d_in[8];
    const float* b2  = (const float*)d_in[9];
    const float* Wo1 = (const float*)d_in[10];
    const float* bo1 = (const float*)d_in[11];
    const float* Wo2 = (const float*)d_in[12];
    const float* bo2 = (const float*)d_in[13];
    const float* Wo3 = (const float*)d_in[14];
    const float* bo3 = (const float*)d_in[15];
    const float* Wq2 = (const float*)d_in[16];
    const float* bq2 = (const float*)d_in[17];
    const float* Wq3 = (const float*)d_in[18];
    const float* bq3 = (const float*)d_in[19];
    float* out = (float*)d_out;

    wprep_kernel<<<512, 256>>>(W2);
    nodeproj_kernel<<<BB*NN, 256>>>(data, act, W1, b1);

    cudaFuncSetAttribute(edge_kernel, cudaFuncAttributeMaxDynamicSharedMemorySize,
                         EDGE_SMEM);
    edge_kernel<<<BB*NN/2, 256, EDGE_SMEM>>>(edges, b2);

    out_kernel<<<BB*NN/OR, 256>>>(Wo1, bo1, Wo2, bo2, Wo3, bo3, Wq2, bq2);
    q_kernel<<<BB, 64>>>(Wq3, bq3, out);
}

// round 6
// speedup vs baseline: 2.4620x; 1.2644x over previous
#include <cuda_runtime.h>
#include <cuda_bf16.h>
#include <cuda_fp16.h>
#include <cstdint>

// ---------------------------------------------------------------- shapes
#define BB   64
#define NN   64
#define DD   24
#define HH   256
#define EPN  63
#define ETOT 4032

// ---------------------------------------------------------------- scratch
__device__ float g_X  [BB*NN*DD];
__device__ float g_Hs [2][BB*NN*HH];
__device__ float g_Hr [2][BB*NN*HH];
__device__ float g_agg[BB*NN*HH];
__device__ float g_Q  [BB*NN];
__device__ __align__(16) __half g_w2t[2][HH*HH];   // fp16(W2^T): [k][n][kk]

// ---------------------------------------------------------------- helpers
__device__ __forceinline__ void mma16816(float* c, const uint32_t* a, const uint32_t* b) {
    asm volatile(
        "mma.sync.aligned.m16n8k16.row.col.f32.f16.f16.f32 "
        "{%0,%1,%2,%3}, {%4,%5,%6,%7}, {%8,%9}, {%0,%1,%2,%3};\n"
        : "+f"(c[0]), "+f"(c[1]), "+f"(c[2]), "+f"(c[3])
        : "r"(a[0]), "r"(a[1]), "r"(a[2]), "r"(a[3]), "r"(b[0]), "r"(b[1]));
}
#define LDM_X4(r, addr) \
    asm volatile("ldmatrix.sync.aligned.m8n8.x4.shared.b16 {%0,%1,%2,%3}, [%4];" \
        : "=r"((r)[0]), "=r"((r)[1]), "=r"((r)[2]), "=r"((r)[3]) : "r"(addr))

__device__ __forceinline__ void cp16(uint32_t dst, const void* src) {
    asm volatile("cp.async.cg.shared.global [%0], [%1], 16;\n" :: "r"(dst), "l"(src) : "memory");
}
#define CP_COMMIT() asm volatile("cp.async.commit_group;\n" ::: "memory")

__device__ __forceinline__ uint32_t smem_u32(const void* p) {
    uint32_t a;
    asm("{ .reg .u64 t; cvta.to.shared.u64 t, %1; cvt.u32.u64 %0, t; }" : "=r"(a) : "l"(p));
    return a;
}
__device__ __forceinline__ uint32_t pack_h2(float x, float y) {
    __half hx = __float2half_rn(x), hy = __float2half_rn(y);
    return ((uint32_t)__half_as_ushort(hy) << 16) | __half_as_ushort(hx);
}

// ---------------------------------------------------------------- W prep: fp16(W2^T)
__global__ __launch_bounds__(256) void wprep_kernel(const float* __restrict__ W2) {
    int k  = blockIdx.x >> 8;
    int c  = blockIdx.x & 255;
    int kk = threadIdx.x;
    g_w2t[k][c*HH + kk] = __float2half_rn(W2[(k*HH + kk)*HH + c]);
}

// ---------------------------------------------------------------- node projections
__global__ __launch_bounds__(256) void nodeproj_kernel(
    const float* __restrict__ data, const float* __restrict__ act,
    const float* __restrict__ W1, const float* __restrict__ b1)
{
    int bn = blockIdx.x;
    int h  = threadIdx.x;
    __shared__ float xs[DD];
    if (h < 16)      xs[h] = data[bn*32 + h];
    else if (h < 24) xs[h] = act [bn*16 + (h-16)];
    __syncthreads();
    if (h < DD) g_X[bn*DD + h] = xs[h];

    float xr[DD];
#pragma unroll
    for (int d = 0; d < DD; d++) xr[d] = xs[d];
#pragma unroll
    for (int k = 0; k < 2; k++) {
        float hs = 0.f, hr = b1[k*HH + h];
#pragma unroll
        for (int d = 0; d < DD; d++) {
            hs = fmaf(xr[d], W1[(k*48 +      d)*HH + h], hs);
            hr = fmaf(xr[d], W1[(k*48 + 24 + d)*HH + h], hr);
        }
        g_Hs[k][bn*HH + h] = hs;
        g_Hr[k][bn*HH + h] = hr;
    }
}

// ---------------------------------------------------------------- edge GEMM
// M=128 (2 receivers x 64), N=256, K=256; fp16 2-pass (aH*bH + aL*bH)
// 512 threads = 16 warps: wm = wid&3 (32-row group), wn = wid>>2 (64-col group)
// K-chunks of 32, 3-stage cp.async ring on B.
#define AST 264                         // A k-stride elems (+8 pad)
#define BST 40                          // B k-stride elems (+8 pad)
#define KC  32
#define A_HI   0
#define A_LO   67584                    // 128*264*2
#define B_OFF  135168
#define BBUF   20480                    // 256*40*2
#define MISC   (B_OFF + 3*BBUF)        // 196608
// misc floats: hrow[512] b2s[256] relw[128] aggsm[512]
#define EDGE_SMEM (MISC + 1408*4)       // 202240

extern __shared__ __align__(16) char smem[];

__device__ __forceinline__ void stageB(const __half* w, int c, int buf,
                                       int tid, uint32_t sb) {
    uint32_t dst = sb + B_OFF + buf*BBUF;
#pragma unroll
    for (int o = 0; o < 2; o++) {
        int opid = tid + o*512;          // 0..1023
        int n = opid >> 2, part = opid & 3;
        cp16(dst + (uint32_t)(n*BST + part*8)*2, w + n*HH + c*KC + part*8);
    }
}

__global__ __launch_bounds__(512, 1) void edge_kernel(
    const float* __restrict__ edges, const float* __restrict__ b2)
{
    const uint32_t sb = smem_u32(smem);
    float* hrow  = (float*)(smem + MISC);
    float* b2s   = (float*)(smem + MISC + 512*4);
    float* relw  = (float*)(smem + MISC + 768*4);
    float* aggsm = (float*)(smem + MISC + 896*4);

    const int tid = threadIdx.x;
    const int wid = tid >> 5, lid = tid & 31;
    const int wm  = wid & 3;             // rows wm*32 .. +32
    const int wn  = wid >> 2;            // cols wn*64 .. +64
    const int qr  = lid >> 2;
    const int qc  = (lid & 3) * 2;
    const int b   = blockIdx.x >> 5;
    const int g   = blockIdx.x & 31;
    const int n0  = 2*g, n1 = 2*g + 1;
    const int recvsel = wm >> 1;

    const int arow    = wm*32 + (lid & 15);
    const int acolsel = (lid & 16) ? 8 : 0;
    const int brow    = wn*64 + ((lid & 16) ? 8 : 0) + (lid & 7);
    const int bksel   = (lid & 8) ? 8 : 0;

    aggsm[tid] = 0.f;

    for (int k = 0; k < 2; k++) {
        __syncthreads();
        hrow[tid] = g_Hr[k][((b<<6) + ((tid < 256) ? n0 : n1))*HH + (tid & 255)];
        if (tid < 256) b2s[tid] = b2[k*HH + tid];
        if (tid < 128) {
            int recv = (tid < 64) ? n0 : n1, jl = tid & 63;
            relw[tid] = (jl < EPN) ? edges[((b*ETOT) + recv*EPN + jl)*2 + k] : 0.f;
        }
        __syncthreads();

        const __half* w2 = g_w2t[k];
        stageB(w2, 0, 0, tid, sb); CP_COMMIT();
        stageB(w2, 1, 1, tid, sb); CP_COMMIT();

        {   // ---- build A = relu(Hs[send]+Hr[recv]) -> fp16 hi/lo (overlaps cp.async)
            int j = tid >> 2, q4 = tid & 3;
            int recv = (j < 64) ? n0 : n1;
            int jl = j & 63;
            int s = jl + (jl >= recv); if (s > 63) s = 63;  // pad row, relw=0
            const float* hs = &g_Hs[k][((b<<6) + s)*HH];
            const float* hr = &hrow[(j >= 64) ? 256 : 0];
            __half* ah = (__half*)(smem + A_HI) + j*AST;
            __half* al = (__half*)(smem + A_LO) + j*AST;
#pragma unroll 8
            for (int kk = q4*64; kk < q4*64 + 64; kk += 4) {
                float4 v = *(const float4*)(hs + kk);
                float r0 = fmaxf(v.x + hr[kk  ], 0.f);
                float r1 = fmaxf(v.y + hr[kk+1], 0.f);
                float r2 = fmaxf(v.z + hr[kk+2], 0.f);
                float r3 = fmaxf(v.w + hr[kk+3], 0.f);
                __half h0 = __float2half_rn(r0), h1 = __float2half_rn(r1);
                __half h2v = __float2half_rn(r2), h3 = __float2half_rn(r3);
                *(uint32_t*)(ah + kk)     = ((uint32_t)__half_as_ushort(h1) << 16) | __half_as_ushort(h0);
                *(uint32_t*)(ah + kk + 2) = ((uint32_t)__half_as_ushort(h3) << 16) | __half_as_ushort(h2v);
                *(uint32_t*)(al + kk)     = pack_h2(r0 - __half2float(h0), r1 - __half2float(h1));
                *(uint32_t*)(al + kk + 2) = pack_h2(r2 - __half2float(h2v), r3 - __half2float(h3));
            }
        }
        __syncthreads();   // A visible

        float acc[2][8][4];
#pragma unroll
        for (int mt = 0; mt < 2; mt++)
#pragma unroll
            for (int nt = 0; nt < 8; nt++)
#pragma unroll
                for (int r = 0; r < 4; r++) acc[mt][nt][r] = 0.f;

        for (int c = 0; c < 8; c++) {
            if (c < 7) asm volatile("cp.async.wait_group 1;\n" ::: "memory");
            else       asm volatile("cp.async.wait_group 0;\n" ::: "memory");
            __syncthreads();   // chunk c visible to all; prior readers retired

            const uint32_t Bh = sb + B_OFF + (c % 3)*BBUF;
#pragma unroll
            for (int kt = 0; kt < 2; kt++) {
                uint32_t aH[2][4], aL[2][4];
#pragma unroll
                for (int mt = 0; mt < 2; mt++) {
                    uint32_t ao = (uint32_t)((arow + mt*16)*AST + c*KC + kt*16 + acolsel)*2;
                    LDM_X4(aH[mt], sb + A_HI + ao);
                    LDM_X4(aL[mt], sb + A_LO + ao);
                }
                uint32_t bH[8][2];
#pragma unroll
                for (int p = 0; p < 4; p++) {
                    uint32_t bo = (uint32_t)((brow + p*16)*BST + kt*16 + bksel)*2;
                    uint32_t t[4];
                    LDM_X4(t, Bh + bo);
                    bH[2*p][0] = t[0];   bH[2*p][1] = t[1];
                    bH[2*p+1][0] = t[2]; bH[2*p+1][1] = t[3];
                }
#pragma unroll
                for (int mt = 0; mt < 2; mt++)
#pragma unroll
                    for (int nt = 0; nt < 8; nt++) {
                        mma16816(acc[mt][nt], aH[mt], bH[nt]);
                        mma16816(acc[mt][nt], aL[mt], bH[nt]);
                    }
            }
            if (c < 6) { stageB(w2, c + 2, (c + 2) % 3, tid, sb); CP_COMMIT(); }
        }

        // ---- epilogue: v = relu(D+b2)*relw, reduce rows, accumulate aggsm
#pragma unroll
        for (int nt = 0; nt < 8; nt++) {
            int col0 = wn*64 + nt*8 + qc;
            float bb0 = b2s[col0], bb1 = b2s[col0 + 1];
            float v0 = 0.f, v1 = 0.f;
#pragma unroll
            for (int mt = 0; mt < 2; mt++) {
                int r0 = wm*32 + mt*16 + qr;
                float w0 = relw[r0], w1 = relw[r0 + 8];
                v0 += w0*fmaxf(acc[mt][nt][0] + bb0, 0.f)
                    + w1*fmaxf(acc[mt][nt][2] + bb0, 0.f);
                v1 += w0*fmaxf(acc[mt][nt][1] + bb1, 0.f)
                    + w1*fmaxf(acc[mt][nt][3] + bb1, 0.f);
            }
            v0 += __shfl_xor_sync(0xffffffffu, v0, 4);
            v0 += __shfl_xor_sync(0xffffffffu, v0, 8);
            v0 += __shfl_xor_sync(0xffffffffu, v0, 16);
            v1 += __shfl_xor_sync(0xffffffffu, v1, 4);
            v1 += __shfl_xor_sync(0xffffffffu, v1, 8);
            v1 += __shfl_xor_sync(0xffffffffu, v1, 16);
            if (lid < 4) {
                atomicAdd(&aggsm[recvsel*256 + col0    ], v0);
                atomicAdd(&aggsm[recvsel*256 + col0 + 1], v1);
            }
        }
    }
    __syncthreads();
    {
        int nn_ = (tid < 256) ? n0 : n1;
        g_agg[((b<<6) + nn_)*HH + (tid & 255)] = aggsm[tid];
    }
}

// ---------------------------------------------------------------- out-MLP: 8 rows/CTA
#define OR 8
__global__ __launch_bounds__(256) void out_kernel(
    const float* __restrict__ Wo1, const float* __restrict__ bo1,
    const float* __restrict__ Wo2, const float* __restrict__ bo2,
    const float* __restrict__ Wo3, const float* __restrict__ bo3,
    const float* __restrict__ Wq2, const float* __restrict__ bq2)
{
    __shared__ __align__(16) float aug[OR][288];
    __shared__ __align__(16) float h1 [OR][264];
    __shared__ __align__(16) float h2 [OR][264];
    __shared__ float pq[OR][24];
    const int bn0 = blockIdx.x * OR;
    const int tid = threadIdx.x;

    {
        int r = tid >> 5, i0 = tid & 31;
        for (int i = i0; i < 280; i += 32)
            aug[r][i] = (i < 24) ? g_X[(bn0+r)*DD + i] : g_agg[(bn0+r)*HH + (i-24)];
    }
    __syncthreads();

    const int col = tid;
    float acc[OR];
#pragma unroll
    for (int r = 0; r < OR; r++) acc[r] = bo1[col];
    for (int i = 0; i < 280; i += 4) {
        float w0 = Wo1[(i  )*HH + col], w1 = Wo1[(i+1)*HH + col];
        float w2 = Wo1[(i+2)*HH + col], w3 = Wo1[(i+3)*HH + col];
#pragma unroll
        for (int r = 0; r < OR; r++) {
            float4 a = *(const float4*)&aug[r][i];
            acc[r] = fmaf(a.x, w0, fmaf(a.y, w1, fmaf(a.z, w2, fmaf(a.w, w3, acc[r]))));
        }
    }
#pragma unroll
    for (int r = 0; r < OR; r++) h1[r][col] = fmaxf(acc[r], 0.f);
    __syncthreads();

#pragma unroll
    for (int r = 0; r < OR; r++) acc[r] = bo2[col];
    for (int i = 0; i < 256; i += 4) {
        float w0 = Wo2[(i  )*HH + col], w1 = Wo2[(i+1)*HH + col];
        float w2 = Wo2[(i+2)*HH + col], w3 = Wo2[(i+3)*HH + col];
#pragma unroll
        for (int r = 0; r < OR; r++) {
            float4 a = *(const float4*)&h1[r][i];
            acc[r] = fmaf(a.x, w0, fmaf(a.y, w1, fmaf(a.z, w2, fmaf(a.w, w3, acc[r]))));
        }
    }
#pragma unroll
    for (int r = 0; r < OR; r++) h2[r][col] = fmaxf(acc[r], 0.f);
    __syncthreads();

    {
        int rr = tid & 7;
        for (int c2 = tid >> 3; c2 < DD; c2 += 32) {
            float s = bo3[c2];
            for (int i = 0; i < 256; i++) s = fmaf(h2[rr][i], Wo3[i*DD + c2], s);
            pq[rr][c2] = (aug[rr][c2] + s) * Wq2[c2];
        }
    }
    __syncthreads();
    if (tid < OR) {
        float q = bq2[0];
#pragma unroll
        for (int d = 0; d < DD; d++) q += pq[tid][d];
        g_Q[bn0 + tid] = q;
    }
}

// ---------------------------------------------------------------- final dot
__global__ void q_kernel(const float* __restrict__ Wq3,
                         const float* __restrict__ bq3,
                         float* __restrict__ out)
{
    const int b = blockIdx.x;
    const int n = threadIdx.x;
    __shared__ float red[64];
    red[n] = g_Q[b*NN + n] * Wq3[n];
    __syncthreads();
    for (int off = 32; off > 0; off >>= 1) {
        if (n < off) red[n] += red[n + off];
        __syncthreads();
    }
    if (n == 0) out[b] = red[0] + bq3[0];
}

// ----------------------------------------------------------------
extern "C" void kernel_launch(void* const* d_in, const int* in_sizes, int n_in,
                              void* d_out, int out_size)
{
    const float* data  = (const float*)d_in[0];
    const float* act   = (const float*)d_in[1];
    const float* edges = (const float*)d_in[2];
    const float* W1  = (const float*)d_in[6];
    const float* b1  = (const float*)d_in[7];
    const float* W2  = (const float*)d_in[8];
    const float* b2  = (const float*)d_in[9];
    const float* Wo1 = (const float*)d_in[10];
    const float* bo1 = (const float*)d_in[11];
    const float* Wo2 = (const float*)d_in[12];
    const float* bo2 = (const float*)d_in[13];
    const float* Wo3 = (const float*)d_in[14];
    const float* bo3 = (const float*)d_in[15];
    const float* Wq2 = (const float*)d_in[16];
    const float* bq2 = (const float*)d_in[17];
    const float* Wq3 = (const float*)d_in[18];
    const float* bq3 = (const float*)d_in[19];
    float* out = (float*)d_out;

    wprep_kernel<<<512, 256>>>(W2);
    nodeproj_kernel<<<BB*NN, 256>>>(data, act, W1, b1);

    cudaFuncSetAttribute(edge_kernel, cudaFuncAttributeMaxDynamicSharedMemorySize,
                         EDGE_SMEM);
    edge_kernel<<<BB*NN/2, 512, EDGE_SMEM>>>(edges, b2);

    out_kernel<<<BB*NN/OR, 256>>>(Wo1, bo1, Wo2, bo2, Wo3, bo3, Wq2, bq2);
    q_kernel<<<BB, 64>>>(Wq3, bq3, out);
}